// round 5
// baseline (speedup 1.0000x reference)
#include <cuda_runtime.h>

#define DIM 2560
#define NHEADS 40
#define HDIM 64
#define BATCH 2
#define SEQ 2048
#define MTOT (BATCH*SEQ)      // 4096
#define QKVN (3*DIM)          // 7680
#define ATT_SCALE 0.125f      // 64^-0.5

// Scratch (device globals — no allocations allowed)
__device__ float g_q[BATCH*NHEADS*SEQ*HDIM];   // [B,H,N,D], pre-scaled by ATT_SCALE
__device__ float g_k[BATCH*NHEADS*SEQ*HDIM];
__device__ float g_v[BATCH*NHEADS*SEQ*HDIM];
__device__ float g_ao[MTOT*DIM];               // attention output, [B,N,C]

// ---------------------------------------------------------------------------
// 128x128x8 tiled fp32 SGEMM, 256 threads, 8x8 micro-tile per thread.
// MODE 0: C = x @ w_qkv + b_qkv, scattered into g_q/g_k/g_v ([B,H,N,D])
// MODE 1: C = g_ao @ w_proj + b_proj, written densely to C
// ---------------------------------------------------------------------------
template<int MODE>
__global__ __launch_bounds__(256)
void sgemm_k(const float* __restrict__ A, const float* __restrict__ Bm,
             const float* __restrict__ bias, float* __restrict__ C,
             int K, int N)
{
    __shared__ float As[8][128];   // transposed A tile
    __shared__ float Bs[8][128];

    const int tid  = threadIdx.x;
    const int row0 = blockIdx.y * 128;
    const int col0 = blockIdx.x * 128;

    const int arow = tid >> 1;          // 0..127
    const int acol = (tid & 1) * 4;     // 0 or 4
    const int brow = tid >> 5;          // 0..7
    const int bcol = (tid & 31) * 4;    // 0..124

    const int ty = tid >> 4;            // 0..15
    const int tx = tid & 15;            // 0..15

    const float* Aeff = (MODE == 1) ? g_ao : A;

    float acc[8][8];
    #pragma unroll
    for (int i = 0; i < 8; i++)
        #pragma unroll
        for (int j = 0; j < 8; j++)
            acc[i][j] = 0.0f;

    const float* Ap = Aeff + (row0 + arow) * K + acol;
    const float* Bp = Bm + brow * N + col0 + bcol;

    for (int k0 = 0; k0 < K; k0 += 8) {
        float4 av = *(const float4*)(Ap + k0);
        float4 bv = *(const float4*)(Bp + k0 * N);
        __syncthreads();
        As[acol + 0][arow] = av.x;
        As[acol + 1][arow] = av.y;
        As[acol + 2][arow] = av.z;
        As[acol + 3][arow] = av.w;
        *(float4*)&Bs[brow][bcol] = bv;
        __syncthreads();

        #pragma unroll
        for (int kk = 0; kk < 8; kk++) {
            float4 a0 = *(const float4*)&As[kk][ty * 4];
            float4 a1 = *(const float4*)&As[kk][ty * 4 + 64];
            float4 b0 = *(const float4*)&Bs[kk][tx * 4];
            float4 b1 = *(const float4*)&Bs[kk][tx * 4 + 64];
            float a[8] = {a0.x, a0.y, a0.z, a0.w, a1.x, a1.y, a1.z, a1.w};
            float b[8] = {b0.x, b0.y, b0.z, b0.w, b1.x, b1.y, b1.z, b1.w};
            #pragma unroll
            for (int i = 0; i < 8; i++)
                #pragma unroll
                for (int j = 0; j < 8; j++)
                    acc[i][j] += a[i] * b[j];
        }
    }

    #pragma unroll
    for (int i = 0; i < 8; i++) {
        int r = row0 + ty * 4 + (i & 3) + (i >> 2) * 64;
        #pragma unroll
        for (int j = 0; j < 8; j++) {
            int c = col0 + tx * 4 + (j & 3) + (j >> 2) * 64;
            float v = acc[i][j] + bias[c];
            if (MODE == 0) {
                int s   = c / DIM;
                int rem = c - s * DIM;
                int h = rem >> 6, d = rem & 63;
                int bb = r >> 11, n = r & (SEQ - 1);
                int idx = (((bb * NHEADS) + h) * SEQ + n) * HDIM + d;
                if (s == 0)      g_q[idx] = v * ATT_SCALE;
                else if (s == 1) g_k[idx] = v;
                else             g_v[idx] = v;
            } else {
                C[r * N + c] = v;
            }
        }
    }
}

// ---------------------------------------------------------------------------
// Flash attention, fp32. One block = one (batch, head, 64 q-rows).
// K-tile of 32 rows per iteration, online softmax, O accumulated in registers.
// ---------------------------------------------------------------------------
__global__ __launch_bounds__(256)
void flash_k()
{
    __shared__ float Qs[64][65];
    __shared__ float Ks[32][65];
    __shared__ float Vs[32][65];
    __shared__ float Ps[64][33];

    const int tid = threadIdx.x;
    const int q0  = blockIdx.x * 64;
    const int h   = blockIdx.y;
    const int bb  = blockIdx.z;
    const int base = ((bb * NHEADS) + h) * SEQ * HDIM;
    const float* qb = g_q + base;
    const float* kb = g_k + base;
    const float* vb = g_v + base;

    // Load Q tile [64 x 64]
    {
        int r  = tid >> 2;
        int c0 = (tid & 3) * 16;
        #pragma unroll
        for (int kx = 0; kx < 4; kx++) {
            float4 v4 = *(const float4*)(qb + (q0 + r) * HDIM + c0 + kx * 4);
            Qs[r][c0 + kx * 4 + 0] = v4.x;
            Qs[r][c0 + kx * 4 + 1] = v4.y;
            Qs[r][c0 + kx * 4 + 2] = v4.z;
            Qs[r][c0 + kx * 4 + 3] = v4.w;
        }
    }

    const int ty = tid >> 4;   // 0..15 -> rows ty*4 .. ty*4+3
    const int tx = tid & 15;   // 0..15

    float m_i[4] = {-1e30f, -1e30f, -1e30f, -1e30f};
    float l_i[4] = {0.f, 0.f, 0.f, 0.f};
    float o[4][4] = {};

    const int lr = tid >> 3;         // 0..31
    const int lc = (tid & 7) * 8;    // 0..56

    for (int kt = 0; kt < SEQ; kt += 32) {
        __syncthreads();   // prior iteration's PV reads of Ks/Vs complete
        {
            float4 a  = *(const float4*)(kb + (kt + lr) * HDIM + lc);
            float4 b2 = *(const float4*)(kb + (kt + lr) * HDIM + lc + 4);
            float4 c2 = *(const float4*)(vb + (kt + lr) * HDIM + lc);
            float4 d2 = *(const float4*)(vb + (kt + lr) * HDIM + lc + 4);
            Ks[lr][lc + 0] = a.x;  Ks[lr][lc + 1] = a.y;
            Ks[lr][lc + 2] = a.z;  Ks[lr][lc + 3] = a.w;
            Ks[lr][lc + 4] = b2.x; Ks[lr][lc + 5] = b2.y;
            Ks[lr][lc + 6] = b2.z; Ks[lr][lc + 7] = b2.w;
            Vs[lr][lc + 0] = c2.x; Vs[lr][lc + 1] = c2.y;
            Vs[lr][lc + 2] = c2.z; Vs[lr][lc + 3] = c2.w;
            Vs[lr][lc + 4] = d2.x; Vs[lr][lc + 5] = d2.y;
            Vs[lr][lc + 6] = d2.z; Vs[lr][lc + 7] = d2.w;
        }
        __syncthreads();

        // S = Q K^T for rows ty*4+ii, cols tx and tx+16  (q pre-scaled)
        float s[4][2] = {};
        #pragma unroll 16
        for (int d = 0; d < HDIM; d++) {
            float qv0 = Qs[ty * 4 + 0][d];
            float qv1 = Qs[ty * 4 + 1][d];
            float qv2 = Qs[ty * 4 + 2][d];
            float qv3 = Qs[ty * 4 + 3][d];
            float kv0 = Ks[tx][d];
            float kv1 = Ks[tx + 16][d];
            s[0][0] += qv0 * kv0;  s[0][1] += qv0 * kv1;
            s[1][0] += qv1 * kv0;  s[1][1] += qv1 * kv1;
            s[2][0] += qv2 * kv0;  s[2][1] += qv2 * kv1;
            s[3][0] += qv3 * kv0;  s[3][1] += qv3 * kv1;
        }

        // Online softmax per row (reduce across the 16 tx lanes; same-ty
        // threads are a contiguous 16-lane group within a warp)
        #pragma unroll
        for (int ii = 0; ii < 4; ii++) {
            float mt = fmaxf(s[ii][0], s[ii][1]);
            mt = fmaxf(mt, __shfl_xor_sync(0xffffffffu, mt, 1));
            mt = fmaxf(mt, __shfl_xor_sync(0xffffffffu, mt, 2));
            mt = fmaxf(mt, __shfl_xor_sync(0xffffffffu, mt, 4));
            mt = fmaxf(mt, __shfl_xor_sync(0xffffffffu, mt, 8));
            float mn    = fmaxf(m_i[ii], mt);
            float alpha = __expf(m_i[ii] - mn);
            m_i[ii] = mn;
            float p0 = __expf(s[ii][0] - mn);
            float p1 = __expf(s[ii][1] - mn);
            float lt = p0 + p1;
            lt += __shfl_xor_sync(0xffffffffu, lt, 1);
            lt += __shfl_xor_sync(0xffffffffu, lt, 2);
            lt += __shfl_xor_sync(0xffffffffu, lt, 4);
            lt += __shfl_xor_sync(0xffffffffu, lt, 8);
            l_i[ii] = l_i[ii] * alpha + lt;
            #pragma unroll
            for (int jd = 0; jd < 4; jd++) o[ii][jd] *= alpha;
            Ps[ty * 4 + ii][tx]      = p0;
            Ps[ty * 4 + ii][tx + 16] = p1;
        }
        __syncthreads();

        // O += P @ V   (O cols d = tx + 16*jd)
        #pragma unroll 8
        for (int j = 0; j < 32; j++) {
            float vv0 = Vs[j][tx];
            float vv1 = Vs[j][tx + 16];
            float vv2 = Vs[j][tx + 32];
            float vv3 = Vs[j][tx + 48];
            #pragma unroll
            for (int ii = 0; ii < 4; ii++) {
                float p = Ps[ty * 4 + ii][j];
                o[ii][0] += p * vv0;
                o[ii][1] += p * vv1;
                o[ii][2] += p * vv2;
                o[ii][3] += p * vv3;
            }
        }
    }

    // Normalize and write [B,N,C]
    #pragma unroll
    for (int ii = 0; ii < 4; ii++) {
        float inv = 1.0f / l_i[ii];
        int n = q0 + ty * 4 + ii;
        float* dst = g_ao + (bb * SEQ + n) * DIM + h * HDIM;
        dst[tx + 0]  = o[ii][0] * inv;
        dst[tx + 16] = o[ii][1] * inv;
        dst[tx + 32] = o[ii][2] * inv;
        dst[tx + 48] = o[ii][3] * inv;
    }
}

extern "C" void kernel_launch(void* const* d_in, const int* in_sizes, int n_in,
                              void* d_out, int out_size)
{
    (void)in_sizes; (void)n_in; (void)out_size;
    const float* x      = (const float*)d_in[0];
    const float* w_qkv  = (const float*)d_in[1];
    const float* b_qkv  = (const float*)d_in[2];
    const float* w_proj = (const float*)d_in[3];
    const float* b_proj = (const float*)d_in[4];
    float* out = (float*)d_out;

    dim3 g1(QKVN / 128, MTOT / 128);   // 60 x 32
    sgemm_k<0><<<g1, 256>>>(x, w_qkv, b_qkv, nullptr, DIM, QKVN);

    dim3 g2(SEQ / 64, NHEADS, BATCH);  // 32 x 40 x 2
    flash_k<<<g2, 256>>>();

    dim3 g3(DIM / 128, MTOT / 128);    // 20 x 32
    sgemm_k<1><<<g3, 256>>>(nullptr, w_proj, b_proj, out, DIM, DIM);
}